// round 1
// baseline (speedup 1.0000x reference)
#include <cuda_runtime.h>
#include <math.h>
#include <stdint.h>

#define BB 8
#define SS 1024
#define EE 512
#define NH 8
#define NQ 16
#define FFN 2048
#define NL 4
#define TT (BB*SS)   // 8192 tokens

// ---------------- scratch (static device globals; no allocation) -------------
__device__ float g_h[TT*EE];          // 16 MB   current hidden state
__device__ float g_attn[TT*NQ];       // 0.5 MB  attention output (16 feats)
__device__ float g_hidden[(size_t)TT*FFN]; // 64 MB ffn hidden (post-relu)
__device__ float g_ffn[TT*EE];        // 16 MB   ffn_out (pre-LN)

// ---------------- helpers ----------------------------------------------------
__device__ __forceinline__ float ex2f(float x) {
    float r;
    asm("ex2.approx.f32 %0, %1;" : "=f"(r) : "f"(x));
    return r;
}

// packed f32x2 FMA (Blackwell dual fp32 pipe): acc = a*b + acc (2 lanes)
__device__ __forceinline__ void ffma2(float2& acc, float a, float2 b) {
    asm("{\n\t"
        ".reg .b64 ra, rb, rc;\n\t"
        "mov.b64 ra, {%2,%2};\n\t"
        "mov.b64 rb, {%3,%4};\n\t"
        "mov.b64 rc, {%0,%1};\n\t"
        "fma.rn.f32x2 rc, ra, rb, rc;\n\t"
        "mov.b64 {%0,%1}, rc;\n\t"
        "}"
        : "+f"(acc.x), "+f"(acc.y)
        : "f"(a), "f"(b.x), "f"(b.y));
}

// block-wide sum over 512 threads, result broadcast to all threads
__device__ __forceinline__ float block_reduce_512(float v, float* red) {
    __syncthreads();  // protect red[] reuse between consecutive calls
    #pragma unroll
    for (int o = 16; o > 0; o >>= 1) v += __shfl_xor_sync(0xffffffffu, v, o);
    int w = threadIdx.x >> 5;
    if ((threadIdx.x & 31) == 0) red[w] = v;
    __syncthreads();
    if (threadIdx.x < 16) {
        float s = red[threadIdx.x];
        #pragma unroll
        for (int o = 8; o > 0; o >>= 1) s += __shfl_xor_sync(0xffffu, s, o);
        if (threadIdx.x == 0) red[0] = s;
    }
    __syncthreads();
    return red[0];
}

// ---------------- K0: h = x + pe ---------------------------------------------
__global__ void k_addpe(const float* __restrict__ x, const float* __restrict__ pe) {
    int i = blockIdx.x * 256 + threadIdx.x;              // float4 index
    const float4* x4 = (const float4*)x;
    const float4* p4 = (const float4*)pe;
    float4 xv = x4[i];
    float4 pv = p4[i % (SS*EE/4)];
    float4 o; o.x = xv.x+pv.x; o.y = xv.y+pv.y; o.z = xv.z+pv.z; o.w = xv.w+pv.w;
    ((float4*)g_h)[i] = o;
}

// ---------------- KA: quantum attention (dk=2 heads, no-max softmax) ---------
// grid (4 qchunks, NH, BB), 256 threads. One thread = one query.
__global__ void k_attn(const float* __restrict__ theta, int l) {
    __shared__ float2 sk[SS];   // keys (= queries = values) for this (b,head)
    int b = blockIdx.z, hh = blockIdx.y, qc = blockIdx.x;

    float ct0 = cosf(theta[l*NQ + 2*hh]);
    float ct1 = cosf(theta[l*NQ + 2*hh + 1]);

    for (int k = threadIdx.x; k < SS; k += 256) {
        const float* hp = &g_h[((size_t)b*SS + k)*EE + 2*hh];
        sk[k] = make_float2(ct0 * cosf(hp[0]), ct1 * cosf(hp[1]));
    }
    __syncthreads();

    int q = qc*256 + threadIdx.x;
    float2 qv = sk[q];
    const float SC = 0.7071067811865476f * 1.4426950408889634f; // (1/sqrt(dk))*log2(e)
    float qm0 = qv.x * SC, qm1 = qv.y * SC;
    float sum = 0.f, a0 = 0.f, a1 = 0.f;
    #pragma unroll 4
    for (int k = 0; k < SS; k++) {
        float2 kv = sk[k];
        float f = fmaf(qm0, kv.x, qm1 * kv.y);
        float e = ex2f(f);                    // exp(score); |score|<=sqrt(2), safe
        sum += e;
        a0 = fmaf(e, kv.x, a0);
        a1 = fmaf(e, kv.y, a1);
    }
    float inv = __frcp_rn(sum);
    float* op = &g_attn[((size_t)b*SS + q)*NQ + 2*hh];
    op[0] = a0 * inv;
    op[1] = a1 * inv;
}

// ---------------- KB: attn @ Wc^T + residual + LN1 (in-place on g_h) --------
// grid 1024 (8 tokens each), 512 threads (one per embedding channel)
__global__ void k_comb_ln(const float* __restrict__ Wc,
                          const float* __restrict__ g1, const float* __restrict__ b1,
                          int l) {
    __shared__ __align__(16) float wcs[NQ*EE];  // [i][e]  32 KB
    __shared__ float asr[8*NQ];
    __shared__ float red[32];
    int t0 = blockIdx.x * 8;
    const float* W = Wc + (size_t)l*EE*NQ;
    for (int idx = threadIdx.x; idx < EE*NQ; idx += 512) {
        int e = idx >> 4, i = idx & 15;
        wcs[i*EE + e] = W[idx];
    }
    for (int idx = threadIdx.x; idx < 8*NQ; idx += 512)
        asr[idx] = g_attn[(size_t)t0*NQ + idx];
    __syncthreads();

    int e = threadIdx.x;
    float wreg[NQ];
    #pragma unroll
    for (int i = 0; i < NQ; i++) wreg[i] = wcs[i*EE + e];
    float gg = g1[l*EE + e], bb = b1[l*EE + e];

    for (int tt = 0; tt < 8; tt++) {
        size_t t = t0 + tt;
        float v = g_h[t*EE + e];
        #pragma unroll
        for (int i = 0; i < NQ; i++) v = fmaf(asr[tt*NQ + i], wreg[i], v);
        float m   = block_reduce_512(v, red) * (1.f/512.f);
        float d   = v - m;
        float var = block_reduce_512(d*d, red) * (1.f/512.f);
        g_h[t*EE + e] = d * rsqrtf(var + 1e-5f) * gg + bb;
    }
}

// ---------------- KC: hidden = relu(qf @ W1^T) -------------------------------
// grid (4 jchunks, 64 token-groups), 256 threads, 128 tokens/block
__global__ void k_ffn1(const float* __restrict__ W1, const float* __restrict__ thf, int l) {
    __shared__ __align__(16) float w1t[NQ*512];   // [i][jl]  32 KB
    __shared__ float qfs[128*NQ];                 // 8 KB
    int jc = blockIdx.x, t0 = blockIdx.y * 128;
    const float* W = W1 + (size_t)l*FFN*NQ + (size_t)jc*512*NQ;
    for (int idx = threadIdx.x; idx < 512*NQ; idx += 256) {
        int jl = idx >> 4, i = idx & 15;
        w1t[i*512 + jl] = W[idx];
    }
    for (int idx = threadIdx.x; idx < 128*NQ; idx += 256) {
        int tt = idx >> 4, i = idx & 15;
        qfs[idx] = cosf(thf[l*NQ + i]) * cosf(g_h[(size_t)(t0 + tt)*EE + i]);
    }
    __syncthreads();
    #pragma unroll
    for (int jj = 0; jj < 2; jj++) {
        int jl = jj*256 + threadIdx.x;
        float w[NQ];
        #pragma unroll
        for (int i = 0; i < NQ; i++) w[i] = w1t[i*512 + jl];
        for (int tt = 0; tt < 128; tt++) {
            float acc = 0.f;
            #pragma unroll
            for (int i = 0; i < NQ; i++) acc = fmaf(qfs[tt*NQ + i], w[i], acc);
            g_hidden[(size_t)(t0 + tt)*FFN + jc*512 + jl] = fmaxf(acc, 0.f);
        }
    }
}

// ---------------- KD: g_ffn = hidden @ W2^T  (M=8192, N=512, K=2048) --------
// TM=64, TN=128, TK=32; 256 threads; 4x8 outputs/thread via packed f32x2 FMA
#define TM 64
#define TN 128
#define TK 32
#define APAD 68
#define BPAD 132
__global__ void k_gemm(const float* __restrict__ W2, int l) {
    __shared__ __align__(16) float As[TK*APAD];   // [k][m]
    __shared__ __align__(16) float Bs[TK*BPAD];   // [k][n]
    int n0 = blockIdx.x * TN;
    int m0 = blockIdx.y * TM;
    const float* Bg = W2 + (size_t)l*EE*FFN;
    int tid = threadIdx.x;
    int tx = tid & 15, ty = tid >> 4;

    float2 acc[4][4];
    #pragma unroll
    for (int i = 0; i < 4; i++)
        #pragma unroll
        for (int j = 0; j < 4; j++) acc[i][j] = make_float2(0.f, 0.f);

    for (int k0 = 0; k0 < FFN; k0 += TK) {
        #pragma unroll
        for (int r = 0; r < 2; r++) {                 // A: 64x32 = 512 float4
            int idx = tid + r*256;
            int m = idx >> 3, k4 = (idx & 7) << 2;
            float4 v = *(const float4*)&g_hidden[(size_t)(m0 + m)*FFN + k0 + k4];
            As[(k4+0)*APAD + m] = v.x;
            As[(k4+1)*APAD + m] = v.y;
            As[(k4+2)*APAD + m] = v.z;
            As[(k4+3)*APAD + m] = v.w;
        }
        #pragma unroll
        for (int r = 0; r < 4; r++) {                 // B: 128x32 = 1024 float4
            int idx = tid + r*256;
            int n = idx >> 3, k4 = (idx & 7) << 2;
            float4 v = *(const float4*)&Bg[(size_t)(n0 + n)*FFN + k0 + k4];
            Bs[(k4+0)*BPAD + n] = v.x;
            Bs[(k4+1)*BPAD + n] = v.y;
            Bs[(k4+2)*BPAD + n] = v.z;
            Bs[(k4+3)*BPAD + n] = v.w;
        }
        __syncthreads();
        #pragma unroll 8
        for (int k = 0; k < TK; k++) {
            float4 av  = *(const float4*)&As[k*APAD + ty*4];
            float4 bv0 = *(const float4*)&Bs[k*BPAD + tx*8];
            float4 bv1 = *(const float4*)&Bs[k*BPAD + tx*8 + 4];
            float  am[4] = {av.x, av.y, av.z, av.w};
            float2 bp[4] = {{bv0.x,bv0.y},{bv0.z,bv0.w},{bv1.x,bv1.y},{bv1.z,bv1.w}};
            #pragma unroll
            for (int mi = 0; mi < 4; mi++)
                #pragma unroll
                for (int ni = 0; ni < 4; ni++)
                    ffma2(acc[mi][ni], am[mi], bp[ni]);
        }
        __syncthreads();
    }
    #pragma unroll
    for (int mi = 0; mi < 4; mi++) {
        float* cp = &g_ffn[(size_t)(m0 + ty*4 + mi)*EE + n0 + tx*8];
        float4 o0 = make_float4(acc[mi][0].x, acc[mi][0].y, acc[mi][1].x, acc[mi][1].y);
        float4 o1 = make_float4(acc[mi][2].x, acc[mi][2].y, acc[mi][3].x, acc[mi][3].y);
        *(float4*)cp       = o0;
        *(float4*)(cp + 4) = o1;
    }
}

// ---------------- KE: h = LN(h + ffn_out) ------------------------------------
// grid 1024 (8 tokens each), 512 threads. Writes d_out on final layer.
__global__ void k_resln(const float* __restrict__ gamma, const float* __restrict__ beta,
                        float* __restrict__ dout, int l, int final_layer) {
    __shared__ float red[32];
    int t0 = blockIdx.x * 8;
    int e = threadIdx.x;
    float gg = gamma[l*EE + e], bb = beta[l*EE + e];
    float* outp = final_layer ? dout : g_h;
    for (int tt = 0; tt < 8; tt++) {
        size_t t = t0 + tt;
        float v = g_h[t*EE + e] + g_ffn[t*EE + e];
        float m   = block_reduce_512(v, red) * (1.f/512.f);
        float d   = v - m;
        float var = block_reduce_512(d*d, red) * (1.f/512.f);
        outp[t*EE + e] = d * rsqrtf(var + 1e-5f) * gg + bb;
    }
}

// ---------------- launch ------------------------------------------------------
extern "C" void kernel_launch(void* const* d_in, const int* in_sizes, int n_in,
                              void* d_out, int out_size) {
    const float* x   = (const float*)d_in[0];
    const float* pe  = (const float*)d_in[1];
    const float* tha = (const float*)d_in[2];
    const float* thf = (const float*)d_in[3];
    const float* Wc  = (const float*)d_in[4];
    const float* W1  = (const float*)d_in[5];
    const float* W2  = (const float*)d_in[6];
    const float* g1  = (const float*)d_in[7];
    const float* b1  = (const float*)d_in[8];
    const float* g2  = (const float*)d_in[9];
    const float* b2  = (const float*)d_in[10];
    float* out = (float*)d_out;

    k_addpe<<<TT*EE/4/256, 256>>>(x, pe);
    for (int l = 0; l < NL; l++) {
        k_attn<<<dim3(4, NH, BB), 256>>>(tha, l);
        k_comb_ln<<<TT/8, 512>>>(Wc, g1, b1, l);
        k_ffn1<<<dim3(4, TT/128), 256>>>(W1, thf, l);
        k_gemm<<<dim3(EE/TN, TT/TM), 256>>>(W2, l);
        k_resln<<<TT/8, 512>>>(g2, b2, out, l, (l == NL-1) ? 1 : 0);
    }
}

// round 3
// speedup vs baseline: 4.0280x; 4.0280x over previous
#include <cuda_runtime.h>
#include <math.h>
#include <stdint.h>

#define BB 8
#define SS 1024
#define EE 512
#define NH 8
#define NQ 16
#define FFN 2048
#define NL 4
#define TT (BB*SS)   // 8192 tokens

// ---------------- scratch (static device globals; no allocation) -------------
__device__ float g_h[TT*EE];               // 16 MB   current hidden state
__device__ float g_attn[TT*NQ];            // 0.5 MB  attention output
__device__ float g_hidden[(size_t)TT*FFN]; // 64 MB   ffn hidden (post-relu, tf32-rounded)
__device__ float g_ffn[TT*EE];             // 16 MB   ffn_out (pre-LN)
__device__ float g_w2r[(size_t)NL*EE*FFN]; // 16 MB   W2 pre-rounded to tf32

// ---------------- PTX helpers -------------------------------------------------
__device__ __forceinline__ float ex2f(float x) {
    float r; asm("ex2.approx.f32 %0, %1;" : "=f"(r) : "f"(x)); return r;
}

__device__ __forceinline__ uint32_t smem_u32(const void* p) {
    uint32_t a;
    asm("{ .reg .u64 t; cvta.to.shared.u64 t, %1; cvt.u32.u64 %0, t; }" : "=r"(a) : "l"(p));
    return a;
}

__device__ __forceinline__ float tf32_round(float x) {
    uint32_t u; asm("cvt.rna.tf32.f32 %0, %1;" : "=r"(u) : "f"(x));
    return __uint_as_float(u);
}

__device__ __forceinline__ void cp16(uint32_t dst, const float* src) {
    asm volatile("cp.async.cg.shared.global [%0], [%1], 16;" :: "r"(dst), "l"(src) : "memory");
}
#define CP_COMMIT() asm volatile("cp.async.commit_group;" ::: "memory")
#define CP_WAIT1()  asm volatile("cp.async.wait_group 1;" ::: "memory")

__device__ __forceinline__ void ldsm4(uint32_t* r, uint32_t a) {
    asm volatile("ldmatrix.sync.aligned.m8n8.x4.shared.b16 {%0,%1,%2,%3}, [%4];"
                 : "=r"(r[0]), "=r"(r[1]), "=r"(r[2]), "=r"(r[3]) : "r"(a));
}
__device__ __forceinline__ void ldsm2(uint32_t* r, uint32_t a) {
    asm volatile("ldmatrix.sync.aligned.m8n8.x2.shared.b16 {%0,%1}, [%2];"
                 : "=r"(r[0]), "=r"(r[1]) : "r"(a));
}
__device__ __forceinline__ void mma_tf32(float* c, const uint32_t* a, const uint32_t* b) {
    asm volatile("mma.sync.aligned.m16n8k8.row.col.f32.tf32.tf32.f32 "
                 "{%0,%1,%2,%3}, {%4,%5,%6,%7}, {%8,%9}, {%0,%1,%2,%3};"
                 : "+f"(c[0]), "+f"(c[1]), "+f"(c[2]), "+f"(c[3])
                 : "r"(a[0]), "r"(a[1]), "r"(a[2]), "r"(a[3]), "r"(b[0]), "r"(b[1]));
}

// ---------------- K0: h = x + pe ---------------------------------------------
__global__ void k_addpe(const float* __restrict__ x, const float* __restrict__ pe) {
    int i = blockIdx.x * 256 + threadIdx.x;
    const float4* x4 = (const float4*)x;
    const float4* p4 = (const float4*)pe;
    float4 xv = x4[i];
    float4 pv = p4[i % (SS*EE/4)];
    float4 o; o.x = xv.x+pv.x; o.y = xv.y+pv.y; o.z = xv.z+pv.z; o.w = xv.w+pv.w;
    ((float4*)g_h)[i] = o;
}

// ---------------- Kcvt: W2 -> tf32-rounded copy -------------------------------
__global__ void k_cvtw2(const float* __restrict__ w2) {
    size_t i = (size_t)blockIdx.x * 256 + threadIdx.x;
    float4 v = ((const float4*)w2)[i];
    float4 o;
    o.x = tf32_round(v.x); o.y = tf32_round(v.y);
    o.z = tf32_round(v.z); o.w = tf32_round(v.w);
    ((float4*)g_w2r)[i] = o;
}

// ---------------- KA: quantum attention (dk=2 heads, no-max softmax) ---------
__global__ void k_attn(const float* __restrict__ theta, int l) {
    __shared__ float2 sk[SS];
    int b = blockIdx.z, hh = blockIdx.y, qc = blockIdx.x;

    float ct0 = cosf(theta[l*NQ + 2*hh]);
    float ct1 = cosf(theta[l*NQ + 2*hh + 1]);

    for (int k = threadIdx.x; k < SS; k += 256) {
        const float* hp = &g_h[((size_t)b*SS + k)*EE + 2*hh];
        sk[k] = make_float2(ct0 * cosf(hp[0]), ct1 * cosf(hp[1]));
    }
    __syncthreads();

    int q = qc*256 + threadIdx.x;
    float2 qv = sk[q];
    const float SC = 0.7071067811865476f * 1.4426950408889634f;  // rsqrt(dk)*log2(e)
    float qm0 = qv.x * SC, qm1 = qv.y * SC;
    float sum = 0.f, a0 = 0.f, a1 = 0.f;
    #pragma unroll 4
    for (int k = 0; k < SS; k++) {
        float2 kv = sk[k];
        float f = fmaf(qm0, kv.x, qm1 * kv.y);
        float e = ex2f(f);
        sum += e;
        a0 = fmaf(e, kv.x, a0);
        a1 = fmaf(e, kv.y, a1);
    }
    float inv = __frcp_rn(sum);
    float* op = &g_attn[((size_t)b*SS + q)*NQ + 2*hh];
    op[0] = a0 * inv;
    op[1] = a1 * inv;
}

// ---------------- KB: attn @ Wc^T + residual + LN1 (warp-per-token) ----------
// block 256 thr = 8 warps; 4 tokens per warp => 32 tokens/block; grid 256
__global__ void __launch_bounds__(256) k_comb_ln(const float* __restrict__ Wc,
                          const float* __restrict__ g1, const float* __restrict__ b1,
                          int l) {
    __shared__ __align__(16) float wcs[NQ*EE];  // [i][e] 32 KB
    __shared__ float sat[32*NQ];                // 2 KB
    int t0 = blockIdx.x * 32;
    const float* W = Wc + (size_t)l*EE*NQ;      // gmem layout [e][i]
    for (int idx = threadIdx.x; idx < EE*NQ; idx += 256) {
        int e = idx >> 4, i = idx & 15;
        wcs[i*EE + e] = W[idx];
    }
    for (int idx = threadIdx.x; idx < 32*NQ; idx += 256)
        sat[idx] = g_attn[(size_t)t0*NQ + idx];
    __syncthreads();

    int w = threadIdx.x >> 5, ln = threadIdx.x & 31;
    int eb = ln * 4;                            // channels: eb + 128*j .. +3
    float4 gv[4], bv[4];
    #pragma unroll
    for (int j = 0; j < 4; j++) {
        gv[j] = *(const float4*)&g1[l*EE + eb + j*128];
        bv[j] = *(const float4*)&b1[l*EE + eb + j*128];
    }

    for (int tt = 0; tt < 4; tt++) {
        int tl = w*4 + tt;
        size_t t = t0 + tl;
        float a[NQ];
        #pragma unroll
        for (int i = 0; i < NQ; i++) a[i] = sat[tl*NQ + i];
        float v[16];
        #pragma unroll
        for (int j = 0; j < 4; j++) {
            float4 hv = *(const float4*)&g_h[t*EE + eb + j*128];
            v[j*4+0] = hv.x; v[j*4+1] = hv.y; v[j*4+2] = hv.z; v[j*4+3] = hv.w;
        }
        #pragma unroll
        for (int i = 0; i < NQ; i++) {
            float ai = a[i];
            #pragma unroll
            for (int j = 0; j < 4; j++) {
                float4 wv = *(const float4*)&wcs[i*EE + eb + j*128];
                v[j*4+0] = fmaf(ai, wv.x, v[j*4+0]);
                v[j*4+1] = fmaf(ai, wv.y, v[j*4+1]);
                v[j*4+2] = fmaf(ai, wv.z, v[j*4+2]);
                v[j*4+3] = fmaf(ai, wv.w, v[j*4+3]);
            }
        }
        float s1 = 0.f, s2 = 0.f;
        #pragma unroll
        for (int j = 0; j < 16; j++) { s1 += v[j]; s2 = fmaf(v[j], v[j], s2); }
        #pragma unroll
        for (int o = 16; o > 0; o >>= 1) {
            s1 += __shfl_xor_sync(0xffffffffu, s1, o);
            s2 += __shfl_xor_sync(0xffffffffu, s2, o);
        }
        float m  = s1 * (1.f/512.f);
        float var = fmaf(-m, m, s2 * (1.f/512.f));
        float rs = rsqrtf(var + 1e-5f);
        #pragma unroll
        for (int j = 0; j < 4; j++) {
            float4 o4;
            o4.x = (v[j*4+0]-m)*rs*gv[j].x + bv[j].x;
            o4.y = (v[j*4+1]-m)*rs*gv[j].y + bv[j].y;
            o4.z = (v[j*4+2]-m)*rs*gv[j].z + bv[j].z;
            o4.w = (v[j*4+3]-m)*rs*gv[j].w + bv[j].w;
            *(float4*)&g_h[t*EE + eb + j*128] = o4;
        }
    }
}

// ---------------- KC: hidden = relu(qf @ W1^T), tf32-rounded -----------------
__global__ void k_ffn1(const float* __restrict__ W1, const float* __restrict__ thf, int l) {
    __shared__ __align__(16) float w1t[NQ*512];
    __shared__ float qfs[128*NQ];
    int jc = blockIdx.x, t0 = blockIdx.y * 128;
    const float* W = W1 + (size_t)l*FFN*NQ + (size_t)jc*512*NQ;
    for (int idx = threadIdx.x; idx < 512*NQ; idx += 256) {
        int jl = idx >> 4, i = idx & 15;
        w1t[i*512 + jl] = W[idx];
    }
    for (int idx = threadIdx.x; idx < 128*NQ; idx += 256) {
        int tt = idx >> 4, i = idx & 15;
        qfs[idx] = cosf(thf[l*NQ + i]) * cosf(g_h[(size_t)(t0 + tt)*EE + i]);
    }
    __syncthreads();
    #pragma unroll
    for (int jj = 0; jj < 2; jj++) {
        int jl = jj*256 + threadIdx.x;
        float w[NQ];
        #pragma unroll
        for (int i = 0; i < NQ; i++) w[i] = w1t[i*512 + jl];
        for (int tt = 0; tt < 128; tt++) {
            float acc = 0.f;
            #pragma unroll
            for (int i = 0; i < NQ; i++) acc = fmaf(qfs[tt*NQ + i], w[i], acc);
            g_hidden[(size_t)(t0 + tt)*FFN + jc*512 + jl] = tf32_round(fmaxf(acc, 0.f));
        }
    }
}

// ---------------- KD: g_ffn = hidden @ W2^T via mma.sync tf32 ----------------
// M=8192, N=512, K=2048. CTA tile 128x128, K-tile 32, 3-stage cp.async.
// 8 warps: warp tile 64x32 (4 m16 x 4 n8 mmas per k8).
#define KT 32
#define STAGE_B 32768u           // A 16KB + B 16KB
#define NKT (FFN/KT)             // 64
#define GSMEM (3*STAGE_B)        // 96 KB

__device__ __forceinline__ void load_stage(uint32_t sb, int buf,
                                           const float* Ag, const float* Bg,
                                           int m0, int n0, int k0, int tid) {
    uint32_t ab = sb + buf*STAGE_B;
    uint32_t bbs = ab + 16384u;
    #pragma unroll
    for (int i = 0; i < 4; i++) {    // A: 128 rows x 128B = 1024 x 16B
        int idx = tid + i*256;
        int row = idx >> 3, q = idx & 7;
        cp16(ab + row*128 + ((q ^ (row & 7)) << 4),
             Ag + (size_t)(m0 + row)*FFN + k0 + q*4);
    }
    #pragma unroll
    for (int i = 0; i < 4; i++) {    // B: 128 rows x 128B
        int idx = tid + i*256;
        int row = idx >> 3, q = idx & 7;
        cp16(bbs + row*128 + ((q ^ (row & 7)) << 4),
             Bg + (size_t)(n0 + row)*FFN + k0 + q*4);
    }
}

__global__ void __launch_bounds__(256, 1) k_gemm(int l) {
    extern __shared__ char sm[];
    uint32_t sb = smem_u32(sm);
    const int tid = threadIdx.x;
    const int w = tid >> 5, ln = tid & 31;
    const int m0 = blockIdx.y * 128, n0 = blockIdx.x * 128;
    const int wm = (w & 1) * 64, wn = (w >> 1) * 32;
    const float* Ag = g_hidden;
    const float* Bg = g_w2r + (size_t)l*EE*FFN;

    float c[4][4][4];
    #pragma unroll
    for (int mi = 0; mi < 4; mi++)
        #pragma unroll
        for (int ni = 0; ni < 4; ni++)
            #pragma unroll
            for (int r = 0; r < 4; r++) c[mi][ni][r] = 0.f;

    const int lr = ln & 7;
    const int lhalf = (ln >> 3) & 1;   // A: m-half select
    const int lq = ln >> 4;            // A: k-quad select
    const int bq = (ln >> 3) & 1;      // B: k-quad select

    load_stage(sb, 0, Ag, Bg, m0, n0, 0, tid);  CP_COMMIT();
    load_stage(sb, 1, Ag, Bg, m0, n0, KT, tid); CP_COMMIT();

    for (int s = 0; s < NKT; s++) {
        CP_WAIT1();
        __syncthreads();
        if (s + 2 < NKT) {
            load_stage(sb, (s+2)%3, Ag, Bg, m0, n0, (s+2)*KT, tid);
            CP_COMMIT();
        }
        uint32_t ab = sb + (s%3)*STAGE_B;
        uint32_t bbs = ab + 16384u;
        #pragma unroll
        for (int ks = 0; ks < 4; ks++) {
            uint32_t afr[4][4], bfr[4][2];
            #pragma unroll
            for (int mi = 0; mi < 4; mi++) {
                int ml = wm + mi*16 + lhalf*8 + lr;
                int q = ks*2 + lq;
                ldsm4(afr[mi], ab + ml*128 + ((q ^ (ml & 7)) << 4));
            }
            #pragma unroll
            for (int ni = 0; ni < 4; ni++) {
                int nl = wn + ni*8 + lr;
                int q = ks*2 + bq;
                ldsm2(bfr[ni], bbs + nl*128 + ((q ^ (nl & 7)) << 4));
            }
            #pragma unroll
            for (int mi = 0; mi < 4; mi++)
                #pragma unroll
                for (int ni = 0; ni < 4; ni++)
                    mma_tf32(c[mi][ni], afr[mi], bfr[ni]);
        }
    }

    // epilogue: direct stores
    #pragma unroll
    for (int mi = 0; mi < 4; mi++) {
        #pragma unroll
        for (int ni = 0; ni < 4; ni++) {
            int row = m0 + wm + mi*16 + (ln >> 2);
            int col = n0 + wn + ni*8 + (ln & 3)*2;
            float2 lo = make_float2(c[mi][ni][0], c[mi][ni][1]);
            float2 hi = make_float2(c[mi][ni][2], c[mi][ni][3]);
            *(float2*)&g_ffn[(size_t)row*EE + col]     = lo;
            *(float2*)&g_ffn[(size_t)(row+8)*EE + col] = hi;
        }
    }
}

// ---------------- KE: h = LN(h + ffn_out), warp-per-token --------------------
__global__ void __launch_bounds__(256) k_resln(const float* __restrict__ gamma,
                        const float* __restrict__ beta,
                        float* __restrict__ dout, int l, int fin) {
    int t0 = blockIdx.x * 32;
    int w = threadIdx.x >> 5, ln = threadIdx.x & 31;
    float* outp = fin ? dout : g_h;
    int eb = ln * 4;
    float4 gv[4], bv[4];
    #pragma unroll
    for (int j = 0; j < 4; j++) {
        gv[j] = *(const float4*)&gamma[l*EE + eb + j*128];
        bv[j] = *(const float4*)&beta[l*EE + eb + j*128];
    }
    for (int tt = 0; tt < 4; tt++) {
        size_t t = t0 + w*4 + tt;
        float v[16]; float s1 = 0.f, s2 = 0.f;
        #pragma unroll
        for (int j = 0; j < 4; j++) {
            float4 hv = *(const float4*)&g_h[t*EE + eb + j*128];
            float4 fv = *(const float4*)&g_ffn[t*EE + eb + j*128];
            v[j*4+0] = hv.x + fv.x; v[j*4+1] = hv.y + fv.y;
            v[j*4+2] = hv.z + fv.z; v[j*4+3] = hv.w + fv.w;
        }
        #pragma unroll
        for (int j = 0; j < 16; j++) { s1 += v[j]; s2 = fmaf(v[j], v[j], s2); }
        #pragma unroll
        for (int o = 16; o > 0; o >>= 1) {
            s1 += __shfl_xor_sync(0xffffffffu, s1, o);
            s2 += __shfl_xor_sync(0xffffffffu, s2, o);
        }
        float m  = s1 * (1.f/512.f);
        float var = fmaf(-m, m, s2 * (1.f/512.f));
        float rs = rsqrtf(var + 1e-5f);
        #pragma unroll
        for (int j = 0; j < 4; j++) {
            float4 o4;
            o4.x = (v[j*4+0]-m)*rs*gv[j].x + bv[j].x;
            o4.y = (v[j*4+1]-m)*rs*gv[j].y + bv[j].y;
            o4.z = (v[j*4+2]-m)*rs*gv[j].z + bv[j].z;
            o4.w = (v[j*4+3]-m)*rs*gv[j].w + bv[j].w;
            *(float4*)&outp[t*EE + eb + j*128] = o4;
        }
    }
}

// ---------------- launch ------------------------------------------------------
extern "C" void kernel_launch(void* const* d_in, const int* in_sizes, int n_in,
                              void* d_out, int out_size) {
    const float* x   = (const float*)d_in[0];
    const float* pe  = (const float*)d_in[1];
    const float* tha = (const float*)d_in[2];
    const float* thf = (const float*)d_in[3];
    const float* Wc  = (const float*)d_in[4];
    const float* W1  = (const float*)d_in[5];
    const float* W2  = (const float*)d_in[6];
    const float* g1  = (const float*)d_in[7];
    const float* b1  = (const float*)d_in[8];
    const float* g2  = (const float*)d_in[9];
    const float* b2  = (const float*)d_in[10];
    float* out = (float*)d_out;

    cudaFuncSetAttribute(k_gemm, cudaFuncAttributeMaxDynamicSharedMemorySize, GSMEM);

    k_addpe<<<TT*EE/4/256, 256>>>(x, pe);
    k_cvtw2<<<(NL*EE*FFN/4)/256, 256>>>(W2);
    for (int l = 0; l < NL; l++) {
        k_attn<<<dim3(4, NH, BB), 256>>>(tha, l);
        k_comb_ln<<<TT/32, 256>>>(Wc, g1, b1, l);
        k_ffn1<<<dim3(4, TT/128), 256>>>(W1, thf, l);
        k_gemm<<<dim3(EE/128, TT/128), 256, GSMEM>>>(l);
        k_resln<<<TT/32, 256>>>(g2, b2, out, l, (l == NL-1) ? 1 : 0);
    }
}

// round 4
// speedup vs baseline: 4.1619x; 1.0332x over previous
#include <cuda_runtime.h>
#include <math.h>
#include <stdint.h>

#define BB 8
#define SS 1024
#define EE 512
#define NH 8
#define NQ 16
#define FFN 2048
#define NL 4
#define TT (BB*SS)   // 8192 tokens

// ---------------- scratch (static device globals; no allocation) -------------
__device__ float g_h[TT*EE];               // 16 MB  current hidden state
__device__ float g_attn[TT*NQ];            // 0.5 MB attention output
__device__ float g_w2r[(size_t)NL*EE*FFN]; // 16 MB  W2 tf32-rounded
__device__ float g_w1r[(size_t)NL*FFN*NQ]; // 0.5 MB W1 tf32-rounded

// ---------------- PTX helpers -------------------------------------------------
__device__ __forceinline__ float ex2f(float x) {
    float r; asm("ex2.approx.f32 %0, %1;" : "=f"(r) : "f"(x)); return r;
}
__device__ __forceinline__ uint32_t smem_u32(const void* p) {
    uint32_t a;
    asm("{ .reg .u64 t; cvta.to.shared.u64 t, %1; cvt.u32.u64 %0, t; }" : "=r"(a) : "l"(p));
    return a;
}
__device__ __forceinline__ float tf32_round(float x) {
    uint32_t u; asm("cvt.rna.tf32.f32 %0, %1;" : "=r"(u) : "f"(x));
    return __uint_as_float(u);
}
__device__ __forceinline__ void cp16(uint32_t dst, const float* src) {
    asm volatile("cp.async.cg.shared.global [%0], [%1], 16;" :: "r"(dst), "l"(src) : "memory");
}
#define CP_COMMIT() asm volatile("cp.async.commit_group;" ::: "memory")
#define CP_WAIT0()  asm volatile("cp.async.wait_group 0;" ::: "memory")

__device__ __forceinline__ void ldsm4(uint32_t* r, uint32_t a) {
    asm volatile("ldmatrix.sync.aligned.m8n8.x4.shared.b16 {%0,%1,%2,%3}, [%4];"
                 : "=r"(r[0]), "=r"(r[1]), "=r"(r[2]), "=r"(r[3]) : "r"(a));
}
__device__ __forceinline__ void mma_tf32(float* c, const uint32_t* a, const uint32_t* b) {
    asm volatile("mma.sync.aligned.m16n8k8.row.col.f32.tf32.tf32.f32 "
                 "{%0,%1,%2,%3}, {%4,%5,%6,%7}, {%8,%9}, {%0,%1,%2,%3};"
                 : "+f"(c[0]), "+f"(c[1]), "+f"(c[2]), "+f"(c[3])
                 : "r"(a[0]), "r"(a[1]), "r"(a[2]), "r"(a[3]), "r"(b[0]), "r"(b[1]));
}

// ---------------- K0: h = x + pe ---------------------------------------------
__global__ void k_addpe(const float* __restrict__ x, const float* __restrict__ pe) {
    int i = blockIdx.x * 256 + threadIdx.x;
    float4 xv = ((const float4*)x)[i];
    float4 pv = ((const float4*)pe)[i % (SS*EE/4)];
    float4 o; o.x = xv.x+pv.x; o.y = xv.y+pv.y; o.z = xv.z+pv.z; o.w = xv.w+pv.w;
    ((float4*)g_h)[i] = o;
}

// ---------------- Kcvt: W2/W1 -> tf32-rounded copies -------------------------
__global__ void k_cvtw2(const float* __restrict__ w2) {
    size_t i = (size_t)blockIdx.x * 256 + threadIdx.x;
    float4 v = ((const float4*)w2)[i];
    float4 o;
    o.x = tf32_round(v.x); o.y = tf32_round(v.y);
    o.z = tf32_round(v.z); o.w = tf32_round(v.w);
    ((float4*)g_w2r)[i] = o;
}
__global__ void k_cvtw1(const float* __restrict__ w1) {
    size_t i = (size_t)blockIdx.x * 256 + threadIdx.x;
    float4 v = ((const float4*)w1)[i];
    float4 o;
    o.x = tf32_round(v.x); o.y = tf32_round(v.y);
    o.z = tf32_round(v.z); o.w = tf32_round(v.w);
    ((float4*)g_w1r)[i] = o;
}

// ---------------- KA: quantum attention (dk=2 heads, no-max softmax) ---------
__global__ void k_attn(const float* __restrict__ theta, int l) {
    __shared__ float2 sk[SS];
    int b = blockIdx.z, hh = blockIdx.y, qc = blockIdx.x;
    float ct0 = cosf(theta[l*NQ + 2*hh]);
    float ct1 = cosf(theta[l*NQ + 2*hh + 1]);
    for (int k = threadIdx.x; k < SS; k += 256) {
        const float* hp = &g_h[((size_t)b*SS + k)*EE + 2*hh];
        sk[k] = make_float2(ct0 * cosf(hp[0]), ct1 * cosf(hp[1]));
    }
    __syncthreads();
    int q = qc*256 + threadIdx.x;
    float2 qv = sk[q];
    const float SC = 0.7071067811865476f * 1.4426950408889634f;
    float qm0 = qv.x * SC, qm1 = qv.y * SC;
    float sum = 0.f, a0 = 0.f, a1 = 0.f;
    #pragma unroll 4
    for (int k = 0; k < SS; k++) {
        float2 kv = sk[k];
        float f = fmaf(qm0, kv.x, qm1 * kv.y);
        float e = ex2f(f);
        sum += e;
        a0 = fmaf(e, kv.x, a0);
        a1 = fmaf(e, kv.y, a1);
    }
    float inv = __frcp_rn(sum);
    float* op = &g_attn[((size_t)b*SS + q)*NQ + 2*hh];
    op[0] = a0 * inv;
    op[1] = a1 * inv;
}

// ---------------- KB: attn @ Wc^T + residual + LN1 (warp-per-token) ----------
__global__ void __launch_bounds__(256) k_comb_ln(const float* __restrict__ Wc,
                          const float* __restrict__ g1, const float* __restrict__ b1,
                          int l) {
    __shared__ __align__(16) float wcs[NQ*EE];  // [i][e] 32 KB
    __shared__ float sat[32*NQ];
    int t0 = blockIdx.x * 32;
    const float* W = Wc + (size_t)l*EE*NQ;      // gmem layout [e][i]
    for (int idx = threadIdx.x; idx < EE*NQ; idx += 256) {
        int e = idx >> 4, i = idx & 15;
        wcs[i*EE + e] = W[idx];
    }
    for (int idx = threadIdx.x; idx < 32*NQ; idx += 256)
        sat[idx] = g_attn[(size_t)t0*NQ + idx];
    __syncthreads();

    int w = threadIdx.x >> 5, ln = threadIdx.x & 31;
    int eb = ln * 4;
    for (int tt = 0; tt < 4; tt++) {
        int tl = w*4 + tt;
        size_t t = t0 + tl;
        float v[16];
        #pragma unroll
        for (int j = 0; j < 4; j++) {
            float4 hv = *(const float4*)&g_h[t*EE + eb + j*128];
            v[j*4+0] = hv.x; v[j*4+1] = hv.y; v[j*4+2] = hv.z; v[j*4+3] = hv.w;
        }
        #pragma unroll
        for (int i = 0; i < NQ; i++) {
            float ai = sat[tl*NQ + i];
            const float4* wp = (const float4*)&wcs[i*EE + eb];
            #pragma unroll
            for (int j = 0; j < 4; j++) {
                float4 wv = wp[32*j];
                v[j*4+0] = fmaf(ai, wv.x, v[j*4+0]);
                v[j*4+1] = fmaf(ai, wv.y, v[j*4+1]);
                v[j*4+2] = fmaf(ai, wv.z, v[j*4+2]);
                v[j*4+3] = fmaf(ai, wv.w, v[j*4+3]);
            }
        }
        float s1 = 0.f, s2 = 0.f;
        #pragma unroll
        for (int j = 0; j < 16; j++) { s1 += v[j]; s2 = fmaf(v[j], v[j], s2); }
        #pragma unroll
        for (int o = 16; o > 0; o >>= 1) {
            s1 += __shfl_xor_sync(0xffffffffu, s1, o);
            s2 += __shfl_xor_sync(0xffffffffu, s2, o);
        }
        float m  = s1 * (1.f/512.f);
        float var = fmaf(-m, m, s2 * (1.f/512.f));
        float rs = rsqrtf(var + 1e-5f);
        #pragma unroll
        for (int j = 0; j < 4; j++) {
            float4 gv = *(const float4*)&g1[l*EE + eb + j*128];
            float4 bv = *(const float4*)&b1[l*EE + eb + j*128];
            float4 o4;
            o4.x = (v[j*4+0]-m)*rs*gv.x + bv.x;
            o4.y = (v[j*4+1]-m)*rs*gv.y + bv.y;
            o4.z = (v[j*4+2]-m)*rs*gv.z + bv.z;
            o4.w = (v[j*4+3]-m)*rs*gv.w + bv.w;
            *(float4*)&g_h[t*EE + eb + j*128] = o4;
        }
    }
}

// ---------------- KF: fused FFN: relu(qf@W1^T)@W2^T + residual + LN2 ---------
// CTA: M=64 tokens x N=512 (full E), Kstage=32, 64 stages, 2-stage cp.async.
// 512 threads = 16 warps. Main warp tile 32x64 (wid&1 -> m, wid>>1 -> n).
// A tile (hidden 64x32) generated per stage via gen-HMMA (qf x W1chunk).
#define FSLOT 73728u              // As 8KB + Bs 64KB
#define FSMEM 147456u
#define FNKT 64

__global__ void __launch_bounds__(512, 1) k_fused(
        const float* __restrict__ thf,
        const float* __restrict__ g2, const float* __restrict__ b2,
        float* __restrict__ dout, int l, int fin) {
    extern __shared__ char sm[];
    uint32_t sb = smem_u32(sm);
    const int tid = threadIdx.x;
    const int wid = tid >> 5, l5 = tid & 31;
    const int t0 = blockIdx.x * 64;
    const float* W2L = g_w2r + (size_t)l*EE*FFN;
    const float* W1L = g_w1r + (size_t)l*FFN*NQ;

    // ---- gen-role constants: m-tile = wid&3, n8-tile = wid>>2 ----
    const int gmt = wid & 3, gnq = wid >> 2;
    const int gr = l5 >> 2, gc = l5 & 3;

    // qf A-fragments (static): a0=(r,c) a1=(r+8,c) a2=(r,c+4) a3=(r+8,c+4), col=ks*8+..
    uint32_t afrg[2][4];
    #pragma unroll
    for (int ks = 0; ks < 2; ks++) {
        #pragma unroll
        for (int d = 0; d < 4; d++) {
            int tok = t0 + gmt*16 + gr + ((d & 1) ? 8 : 0);
            int i = ks*8 + gc + ((d >> 1) ? 4 : 0);
            float qv = cosf(thf[l*NQ + i]) * cosf(g_h[(size_t)tok*EE + i]);
            afrg[ks][d] = __float_as_uint(tf32_round(qv));
        }
    }

    // ---- main-role constants ----
    const int wm = (wid & 1) * 32, wn = (wid >> 1) * 64;
    const int lr = l5 & 7, lh = (l5 >> 3) & 1, lq = l5 >> 4;

    float c[2][8][4];
    #pragma unroll
    for (int mi = 0; mi < 2; mi++)
        #pragma unroll
        for (int ni = 0; ni < 8; ni++)
            #pragma unroll
            for (int r = 0; r < 4; r++) c[mi][ni][r] = 0.f;

    // B stage loader: 64KB = 8 cp16/thread
    auto loadB = [&](int slot, int k0) {
        uint32_t bbs = sb + slot*FSLOT + 8192u;
        #pragma unroll
        for (int i = 0; i < 8; i++) {
            int idx = tid + i*512;
            int row = idx >> 3, qd = idx & 7;
            cp16(bbs + row*128 + ((qd ^ (row & 7)) << 4),
                 W2L + (size_t)row*FFN + k0 + qd*4);
        }
    };
    // W1 b-frag loader (4 direct LDGs): b0=(k=i',n=ko), rows=i, cols=k_out
    auto loadW1 = [&](int k0, float* w) {
        const float* p = W1L + (size_t)(k0 + gnq*8 + gr)*NQ;
        #pragma unroll
        for (int ks = 0; ks < 2; ks++) {
            w[ks*2+0] = p[ks*8 + gc];
            w[ks*2+1] = p[ks*8 + gc + 4];
        }
    };

    float w1cur[4], w1nxt[4];
    loadB(0, 0); CP_COMMIT();
    loadW1(0, w1cur);

    for (int s = 0; s < FNKT; s++) {
        CP_WAIT0();
        __syncthreads();
        if (s + 1 < FNKT) { loadB((s+1)&1, (s+1)*32); CP_COMMIT(); loadW1((s+1)*32, w1nxt); }

        // ---- generate A_s = relu(qf @ W1chunk^T), tf32, into As[s&1] ----
        uint32_t Asb = sb + (s&1)*FSLOT;
        {
            float ga[4] = {0.f, 0.f, 0.f, 0.f};
            #pragma unroll
            for (int ks = 0; ks < 2; ks++) {
                uint32_t bfr[2] = {__float_as_uint(w1cur[ks*2]),
                                   __float_as_uint(w1cur[ks*2+1])};
                mma_tf32(ga, afrg[ks], bfr);
            }
            #pragma unroll
            for (int r = 0; r < 4; r++)
                ga[r] = tf32_round(fmaxf(ga[r], 0.f));
            int row0 = gmt*16 + gr;
            int col  = gnq*8 + gc*2;
            int q = col >> 2, co = (col & 3) * 4;
            uint32_t a0 = Asb + row0*128 + ((q ^ (row0 & 7)) << 4) + co;
            uint32_t a1 = Asb + (row0+8)*128 + ((q ^ ((row0+8) & 7)) << 4) + co;
            *(float2*)(sm + (a0 - sb)) = make_float2(ga[0], ga[1]);
            *(float2*)(sm + (a1 - sb)) = make_float2(ga[2], ga[3]);
        }
        w1cur[0]=w1nxt[0]; w1cur[1]=w1nxt[1]; w1cur[2]=w1nxt[2]; w1cur[3]=w1nxt[3];
        __syncthreads();

        // ---- main mma: 32x64 warp tile over k=32 ----
        uint32_t Bsb = Asb + 8192u;
        #pragma unroll
        for (int ks = 0; ks < 4; ks++) {
            uint32_t afr[2][4], bfr[4][4];
            #pragma unroll
            for (int mi = 0; mi < 2; mi++) {
                int row = wm + mi*16 + lr + lh*8;
                int q = ks*2 + lq;
                ldsm4(afr[mi], Asb + row*128 + ((q ^ (row & 7)) << 4));
            }
            #pragma unroll
            for (int g = 0; g < 4; g++) {
                int row = wn + g*16 + lr + lq*8;
                int q = ks*2 + lh;
                ldsm4(bfr[g], Bsb + row*128 + ((q ^ (row & 7)) << 4));
            }
            #pragma unroll
            for (int mi = 0; mi < 2; mi++)
                #pragma unroll
                for (int g = 0; g < 4; g++) {
                    mma_tf32(c[mi][2*g],   afr[mi], &bfr[g][0]);
                    mma_tf32(c[mi][2*g+1], afr[mi], &bfr[g][2]);
                }
        }
    }

    // ---- epilogue: stage accums to smem (stride 516 floats), then LN ----
    __syncthreads();
    float* ep = (float*)sm;
    #pragma unroll
    for (int mi = 0; mi < 2; mi++)
        #pragma unroll
        for (int ni = 0; ni < 8; ni++) {
            int row = wm + mi*16 + (l5 >> 2);
            int col = wn + ni*8 + (l5 & 3)*2;
            *(float2*)&ep[row*516 + col]     = make_float2(c[mi][ni][0], c[mi][ni][1]);
            *(float2*)&ep[(row+8)*516 + col] = make_float2(c[mi][ni][2], c[mi][ni][3]);
        }
    __syncthreads();

    float* outp = fin ? dout : g_h;
    int eb = l5 * 4;
    #pragma unroll
    for (int tt = 0; tt < 4; tt++) {
        int tl = wid*4 + tt;
        size_t t = t0 + tl;
        float v[16]; float s1 = 0.f, s2 = 0.f;
        #pragma unroll
        for (int j = 0; j < 4; j++) {
            float4 hv = *(const float4*)&g_h[t*EE + eb + j*128];
            float4 fv = *(const float4*)&ep[tl*516 + eb + j*128];
            v[j*4+0] = hv.x + fv.x; v[j*4+1] = hv.y + fv.y;
            v[j*4+2] = hv.z + fv.z; v[j*4+3] = hv.w + fv.w;
        }
        #pragma unroll
        for (int j = 0; j < 16; j++) { s1 += v[j]; s2 = fmaf(v[j], v[j], s2); }
        #pragma unroll
        for (int o = 16; o > 0; o >>= 1) {
            s1 += __shfl_xor_sync(0xffffffffu, s1, o);
            s2 += __shfl_xor_sync(0xffffffffu, s2, o);
        }
        float m  = s1 * (1.f/512.f);
        float var = fmaf(-m, m, s2 * (1.f/512.f));
        float rs = rsqrtf(var + 1e-5f);
        #pragma unroll
        for (int j = 0; j < 4; j++) {
            float4 gv = *(const float4*)&g2[l*EE + eb + j*128];
            float4 bv = *(const float4*)&b2[l*EE + eb + j*128];
            float4 o4;
            o4.x = (v[j*4+0]-m)*rs*gv.x + bv.x;
            o4.y = (v[j*4+1]-m)*rs*gv.y + bv.y;
            o4.z = (v[j*4+2]-m)*rs*gv.z + bv.z;
            o4.w = (v[j*4+3]-m)*rs*gv.w + bv.w;
            *(float4*)&outp[t*EE + eb + j*128] = o4;
        }
    }
}

// ---------------- launch ------------------------------------------------------
extern "C" void kernel_launch(void* const* d_in, const int* in_sizes, int n_in,
                              void* d_out, int out_size) {
    const float* x   = (const float*)d_in[0];
    const float* pe  = (const float*)d_in[1];
    const float* tha = (const float*)d_in[2];
    const float* thf = (const float*)d_in[3];
    const float* Wc  = (const float*)d_in[4];
    const float* W1  = (const float*)d_in[5];
    const float* W2  = (const float*)d_in[6];
    const float* g1  = (const float*)d_in[7];
    const float* b1  = (const float*)d_in[8];
    const float* g2  = (const float*)d_in[9];
    const float* b2  = (const float*)d_in[10];
    float* out = (float*)d_out;

    cudaFuncSetAttribute(k_fused, cudaFuncAttributeMaxDynamicSharedMemorySize, FSMEM);

    k_addpe<<<TT*EE/4/256, 256>>>(x, pe);
    k_cvtw2<<<(NL*EE*FFN/4)/256, 256>>>(W2);
    k_cvtw1<<<(NL*FFN*NQ/4)/256, 256>>>(W1);
    for (int l = 0; l < NL; l++) {
        k_attn<<<dim3(4, NH, BB), 256>>>(tha, l);
        k_comb_ln<<<TT/32, 256>>>(Wc, g1, b1, l);
        k_fused<<<TT/64, 512, FSMEM>>>(thf, g2, b2, out, l, (l == NL-1) ? 1 : 0);
    }
}

// round 5
// speedup vs baseline: 6.9408x; 1.6677x over previous
#include <cuda_runtime.h>
#include <cuda_fp16.h>
#include <math.h>
#include <stdint.h>

#define BB 8
#define SS 1024
#define EE 512
#define NH 8
#define NQ 16
#define FFN 2048
#define NL 4
#define TT (BB*SS)   // 8192 tokens

// ---------------- scratch (static device globals; no allocation) -------------
__device__ float g_h[TT*EE];                 // 16 MB  current hidden state
__device__ float g_attn[TT*NQ];              // 0.5 MB attention output
__device__ __half g_w2h[(size_t)NL*EE*FFN];  // 8 MB   W2 in fp16
__device__ __half g_w1h[(size_t)NL*FFN*NQ];  // 256 KB W1 in fp16

// ---------------- PTX helpers -------------------------------------------------
__device__ __forceinline__ float ex2f(float x) {
    float r; asm("ex2.approx.f32 %0, %1;" : "=f"(r) : "f"(x)); return r;
}
__device__ __forceinline__ uint32_t smem_u32(const void* p) {
    uint32_t a;
    asm("{ .reg .u64 t; cvta.to.shared.u64 t, %1; cvt.u32.u64 %0, t; }" : "=r"(a) : "l"(p));
    return a;
}
__device__ __forceinline__ uint32_t pack_h2(float a, float b) {
    __half2 h = __floats2half2_rn(a, b);
    return *(uint32_t*)&h;
}
__device__ __forceinline__ void cp16(uint32_t dst, const void* src) {
    asm volatile("cp.async.cg.shared.global [%0], [%1], 16;" :: "r"(dst), "l"(src) : "memory");
}
#define CP_COMMIT() asm volatile("cp.async.commit_group;" ::: "memory")
#define CP_WAIT0()  asm volatile("cp.async.wait_group 0;" ::: "memory")

__device__ __forceinline__ void ldsm4(uint32_t* r, uint32_t a) {
    asm volatile("ldmatrix.sync.aligned.m8n8.x4.shared.b16 {%0,%1,%2,%3}, [%4];"
                 : "=r"(r[0]), "=r"(r[1]), "=r"(r[2]), "=r"(r[3]) : "r"(a));
}
// fp16 mma, fp32 accumulate
__device__ __forceinline__ void mma_f16(float* c, const uint32_t* a, uint32_t b0, uint32_t b1) {
    asm volatile("mma.sync.aligned.m16n8k16.row.col.f32.f16.f16.f32 "
                 "{%0,%1,%2,%3}, {%4,%5,%6,%7}, {%8,%9}, {%0,%1,%2,%3};"
                 : "+f"(c[0]), "+f"(c[1]), "+f"(c[2]), "+f"(c[3])
                 : "r"(a[0]), "r"(a[1]), "r"(a[2]), "r"(a[3]), "r"(b0), "r"(b1));
}

// ---------------- K0: h = x + pe ---------------------------------------------
__global__ void k_addpe(const float* __restrict__ x, const float* __restrict__ pe) {
    int i = blockIdx.x * 256 + threadIdx.x;
    float4 xv = ((const float4*)x)[i];
    float4 pv = ((const float4*)pe)[i % (SS*EE/4)];
    float4 o; o.x = xv.x+pv.x; o.y = xv.y+pv.y; o.z = xv.z+pv.z; o.w = xv.w+pv.w;
    ((float4*)g_h)[i] = o;
}

// ---------------- Kcvt: W2/W1 -> fp16 copies ---------------------------------
__global__ void k_cvtw2(const float* __restrict__ w2) {
    size_t i = (size_t)blockIdx.x * 256 + threadIdx.x;
    float4 v = ((const float4*)w2)[i];
    ((uint32_t*)g_w2h)[2*i]   = pack_h2(v.x, v.y);
    ((uint32_t*)g_w2h)[2*i+1] = pack_h2(v.z, v.w);
}
__global__ void k_cvtw1(const float* __restrict__ w1) {
    size_t i = (size_t)blockIdx.x * 256 + threadIdx.x;
    float4 v = ((const float4*)w1)[i];
    ((uint32_t*)g_w1h)[2*i]   = pack_h2(v.x, v.y);
    ((uint32_t*)g_w1h)[2*i+1] = pack_h2(v.z, v.w);
}

// ---------------- KA: quantum attention, 2-way key split ---------------------
// block 512 thr: 256 queries x 2 key-halves. grid (4, NH, BB).
__global__ void __launch_bounds__(512) k_attn(const float* __restrict__ theta, int l) {
    __shared__ float2 sk[SS];
    __shared__ float4 pp[256];
    int b = blockIdx.z, hh = blockIdx.y, qc = blockIdx.x;
    float ct0 = cosf(theta[l*NQ + 2*hh]);
    float ct1 = cosf(theta[l*NQ + 2*hh + 1]);
    for (int k = threadIdx.x; k < SS; k += 512) {
        const float* hp = &g_h[((size_t)b*SS + k)*EE + 2*hh];
        sk[k] = make_float2(ct0 * cosf(hp[0]), ct1 * cosf(hp[1]));
    }
    __syncthreads();
    int qi = threadIdx.x & 255;
    int half = threadIdx.x >> 8;
    int q = qc*256 + qi;
    float2 qv = sk[q];
    const float SC = 0.7071067811865476f * 1.4426950408889634f;
    float qm0 = qv.x * SC, qm1 = qv.y * SC;
    float sum = 0.f, a0 = 0.f, a1 = 0.f;
    int k0 = half * 512;
    #pragma unroll 4
    for (int k = k0; k < k0 + 512; k++) {
        float2 kv = sk[k];
        float f = fmaf(qm0, kv.x, qm1 * kv.y);
        float e = ex2f(f);
        sum += e;
        a0 = fmaf(e, kv.x, a0);
        a1 = fmaf(e, kv.y, a1);
    }
    if (half == 1) pp[qi] = make_float4(sum, a0, a1, 0.f);
    __syncthreads();
    if (half == 0) {
        float4 o = pp[qi];
        sum += o.x; a0 += o.y; a1 += o.z;
        float inv = __frcp_rn(sum);
        float* op = &g_attn[((size_t)b*SS + q)*NQ + 2*hh];
        op[0] = a0 * inv;
        op[1] = a1 * inv;
    }
}

// ---------------- KB: attn @ Wc^T + residual + LN1 (warp-per-token) ----------
__global__ void __launch_bounds__(256) k_comb_ln(const float* __restrict__ Wc,
                          const float* __restrict__ g1, const float* __restrict__ b1,
                          int l) {
    __shared__ __align__(16) float wcs[NQ*EE];
    __shared__ float sat[32*NQ];
    int t0 = blockIdx.x * 32;
    const float* W = Wc + (size_t)l*EE*NQ;
    for (int idx = threadIdx.x; idx < EE*NQ; idx += 256) {
        int e = idx >> 4, i = idx & 15;
        wcs[i*EE + e] = W[idx];
    }
    for (int idx = threadIdx.x; idx < 32*NQ; idx += 256)
        sat[idx] = g_attn[(size_t)t0*NQ + idx];
    __syncthreads();

    int w = threadIdx.x >> 5, ln = threadIdx.x & 31;
    int eb = ln * 4;
    for (int tt = 0; tt < 4; tt++) {
        int tl = w*4 + tt;
        size_t t = t0 + tl;
        float v[16];
        #pragma unroll
        for (int j = 0; j < 4; j++) {
            float4 hv = *(const float4*)&g_h[t*EE + eb + j*128];
            v[j*4+0] = hv.x; v[j*4+1] = hv.y; v[j*4+2] = hv.z; v[j*4+3] = hv.w;
        }
        #pragma unroll
        for (int i = 0; i < NQ; i++) {
            float ai = sat[tl*NQ + i];
            const float4* wp = (const float4*)&wcs[i*EE + eb];
            #pragma unroll
            for (int j = 0; j < 4; j++) {
                float4 wv = wp[32*j];
                v[j*4+0] = fmaf(ai, wv.x, v[j*4+0]);
                v[j*4+1] = fmaf(ai, wv.y, v[j*4+1]);
                v[j*4+2] = fmaf(ai, wv.z, v[j*4+2]);
                v[j*4+3] = fmaf(ai, wv.w, v[j*4+3]);
            }
        }
        float s1 = 0.f, s2 = 0.f;
        #pragma unroll
        for (int j = 0; j < 16; j++) { s1 += v[j]; s2 = fmaf(v[j], v[j], s2); }
        #pragma unroll
        for (int o = 16; o > 0; o >>= 1) {
            s1 += __shfl_xor_sync(0xffffffffu, s1, o);
            s2 += __shfl_xor_sync(0xffffffffu, s2, o);
        }
        float m  = s1 * (1.f/512.f);
        float var = fmaf(-m, m, s2 * (1.f/512.f));
        float rs = rsqrtf(var + 1e-5f);
        #pragma unroll
        for (int j = 0; j < 4; j++) {
            float4 gv = *(const float4*)&g1[l*EE + eb + j*128];
            float4 bv = *(const float4*)&b1[l*EE + eb + j*128];
            float4 o4;
            o4.x = (v[j*4+0]-m)*rs*gv.x + bv.x;
            o4.y = (v[j*4+1]-m)*rs*gv.y + bv.y;
            o4.z = (v[j*4+2]-m)*rs*gv.z + bv.z;
            o4.w = (v[j*4+3]-m)*rs*gv.w + bv.w;
            *(float4*)&g_h[t*EE + eb + j*128] = o4;
        }
    }
}

// ---------------- KF: fused FFN (fp16 mma): relu(qf@W1^T)@W2^T + res + LN2 ---
// CTA: M=64 tokens x N=512 (full E). K-tile 64 halfs (128B rows), 32 stages,
// 2-stage cp.async. 512 threads = 16 warps; main warp tile 32x64.
// A tile generated per stage: 1 fp16 gen-mma per (16tok x 8col) tile (K=16=NQ).
#define FSLOT 73728u              // As 8KB (64x128B) + Bs 64KB (512x128B)
#define FSMEM 147456u
#define FNKT 32

__global__ void __launch_bounds__(512, 1) k_fused(
        const float* __restrict__ thf,
        const float* __restrict__ g2, const float* __restrict__ b2,
        float* __restrict__ dout, int l, int fin) {
    extern __shared__ char sm[];
    uint32_t sb = smem_u32(sm);
    const int tid = threadIdx.x;
    const int wid = tid >> 5, l5 = tid & 31;
    const int t0 = blockIdx.x * 64;
    const __half* W2L = g_w2h + (size_t)l*EE*FFN;
    const __half* W1L = g_w1h + (size_t)l*FFN*NQ;

    // ---- gen-role: m-tile = wid&3 (16 tokens), n8 pair base = (wid>>2)*2 ----
    const int gmt = wid & 3, gnt = (wid >> 2) * 2;
    const int gr = l5 >> 2, gc = l5 & 3;

    // qf A-fragment (static, fp16 m16n8k16 layout, K=16=NQ)
    uint32_t afrg[4];
    {
        float th[4];
        #pragma unroll
        for (int d = 0; d < 2; d++) {
            th[2*d]   = cosf(thf[l*NQ + 2*gc + 8*d]);
            th[2*d+1] = cosf(thf[l*NQ + 2*gc + 1 + 8*d]);
        }
        #pragma unroll
        for (int rr = 0; rr < 2; rr++) {      // token row r / r+8
            int tok = t0 + gmt*16 + gr + 8*rr;
            const float* hp = &g_h[(size_t)tok*EE];
            #pragma unroll
            for (int kk = 0; kk < 2; kk++) {  // k cols 2c / 2c+8
                float q0 = th[2*kk]   * cosf(hp[2*gc + 8*kk]);
                float q1 = th[2*kk+1] * cosf(hp[2*gc + 1 + 8*kk]);
                afrg[kk*2 + rr] = pack_h2(q0, q1);
            }
        }
    }

    // ---- main-role constants ----
    const int wm = (wid & 1) * 32, wn = (wid >> 1) * 64;
    const int lr = l5 & 7, lh = (l5 >> 3) & 1, lq = l5 >> 4;

    float c[2][8][4];
    #pragma unroll
    for (int mi = 0; mi < 2; mi++)
        #pragma unroll
        for (int ni = 0; ni < 8; ni++)
            #pragma unroll
            for (int r = 0; r < 4; r++) c[mi][ni][r] = 0.f;

    // B stage loader: 64KB = 4096 x 16B = 8 cp16/thread
    auto loadB = [&](int slot, int k0) {
        uint32_t bbs = sb + slot*FSLOT + 8192u;
        #pragma unroll
        for (int i = 0; i < 8; i++) {
            int idx = tid + i*512;
            int row = idx >> 3, qd = idx & 7;
            cp16(bbs + row*128 + ((qd ^ (row & 7)) << 4),
                 W2L + (size_t)row*FFN + k0 + qd*8);
        }
    };

    loadB(0, 0); CP_COMMIT();

    for (int s = 0; s < FNKT; s++) {
        CP_WAIT0();
        __syncthreads();
        if (s + 1 < FNKT) { loadB((s+1)&1, (s+1)*64); CP_COMMIT(); }

        // ---- generate A_s (64 tok x 64 hidden cols), fp16 into As slot ----
        uint32_t Asb = sb + (s&1)*FSLOT;
        #pragma unroll
        for (int jj = 0; jj < 2; jj++) {
            int nt = gnt + jj;                      // n8 tile 0..7
            int jglob = s*64 + nt*8 + gr;           // hidden col
            const uint32_t* wp = (const uint32_t*)(W1L + (size_t)jglob*NQ);
            uint32_t b0 = wp[gc], b1 = wp[gc + 4];
            float ga[4] = {0.f, 0.f, 0.f, 0.f};
            mma_f16(ga, afrg, b0, b1);
            #pragma unroll
            for (int r = 0; r < 4; r++) ga[r] = fmaxf(ga[r], 0.f);
            int row0 = gmt*16 + gr;
            uint32_t byte = (uint32_t)(nt*16 + 4*gc);
            uint32_t q = byte >> 4, off = byte & 15;
            uint32_t a0 = Asb + row0*128 + ((q ^ (row0 & 7)) << 4) + off;
            uint32_t a1 = Asb + (row0+8)*128 + ((q ^ ((row0+8) & 7)) << 4) + off;
            *(uint32_t*)(sm + (a0 - sb)) = pack_h2(ga[0], ga[1]);
            *(uint32_t*)(sm + (a1 - sb)) = pack_h2(ga[2], ga[3]);
        }
        __syncthreads();

        // ---- main mma: 32x64 warp tile over k=64 (4 k16 steps) ----
        uint32_t Bsb = Asb + 8192u;
        #pragma unroll
        for (int ks = 0; ks < 4; ks++) {
            uint32_t afr[2][4], bfr[4][4];
            #pragma unroll
            for (int mi = 0; mi < 2; mi++) {
                int row = wm + mi*16 + lr + lh*8;
                int q = 2*ks + lq;
                ldsm4(afr[mi], Asb + row*128 + ((q ^ (row & 7)) << 4));
            }
            #pragma unroll
            for (int g = 0; g < 4; g++) {
                int row = wn + g*16 + lr + lh*8;
                int q = 2*ks + lq;
                ldsm4(bfr[g], Bsb + row*128 + ((q ^ (row & 7)) << 4));
            }
            #pragma unroll
            for (int mi = 0; mi < 2; mi++)
                #pragma unroll
                for (int g = 0; g < 4; g++) {
                    mma_f16(c[mi][2*g],   afr[mi], bfr[g][0], bfr[g][2]);
                    mma_f16(c[mi][2*g+1], afr[mi], bfr[g][1], bfr[g][3]);
                }
        }
    }

    // ---- epilogue: stage accums to smem (stride 516 floats), then LN ----
    __syncthreads();
    float* ep = (float*)sm;
    #pragma unroll
    for (int mi = 0; mi < 2; mi++)
        #pragma unroll
        for (int ni = 0; ni < 8; ni++) {
            int row = wm + mi*16 + (l5 >> 2);
            int col = wn + ni*8 + (l5 & 3)*2;
            *(float2*)&ep[row*516 + col]     = make_float2(c[mi][ni][0], c[mi][ni][1]);
            *(float2*)&ep[(row+8)*516 + col] = make_float2(c[mi][ni][2], c[mi][ni][3]);
        }
    __syncthreads();

    float* outp = fin ? dout : g_h;
    int eb = l5 * 4;
    #pragma unroll
    for (int tt = 0; tt < 4; tt++) {
        int tl = wid*4 + tt;
        size_t t = t0 + tl;
        float v[16]; float s1 = 0.f, s2 = 0.f;
        #pragma unroll
        for (int j = 0; j < 4; j++) {
            float4 hv = *(const float4*)&g_h[t*EE + eb + j*128];
            float4 fv = *(const float4*)&ep[tl*516 + eb + j*128];
            v[j*4+0] = hv.x + fv.x; v[j*4+1] = hv.y + fv.y;
            v[j*4+2] = hv.z + fv.z; v[j*4+3] = hv.w + fv.w;
        }
        #pragma unroll
        for (int j = 0; j < 16; j++) { s1 += v[j]; s2 = fmaf(v[j], v[j], s2); }
        #pragma unroll
        for (int o = 16; o > 0; o >>= 1) {
            s1 += __shfl_xor_sync(0xffffffffu, s1, o);
            s2 += __shfl_xor_sync(0xffffffffu, s2, o);
        }
        float m  = s1 * (1.f/512.f);
        float var = fmaf(-m, m, s2 * (1.f/512.f));
        float rs = rsqrtf(var + 1e-5f);
        #pragma unroll
        for (int j = 0; j < 4; j++) {
            float4 gv = *(const float4*)&g2[l*EE + eb + j*128];
            float4 bv = *(const float4*)&b2[l*EE + eb + j*128];
            float4 o4;
            o4.x = (v[j*4+0]-m)*rs*gv.x + bv.x;
            o4.y = (v[j*4+1]-m)*rs*gv.y + bv.y;
            o4.z = (v[j*4+2]-m)*rs*gv.z + bv.z;
            o4.w = (v[j*4+3]-m)*rs*gv.w + bv.w;
            *(float4*)&outp[t*EE + eb + j*128] = o4;
        }
    }
}

// ---------------- launch ------------------------------------------------------
extern "C" void kernel_launch(void* const* d_in, const int* in_sizes, int n_in,
                              void* d_out, int out_size) {
    const float* x   = (const float*)d_in[0];
    const float* pe  = (const float*)d_in[1];
    const float* tha = (const float*)d_in[2];
    const float* thf = (const float*)d_in[3];
    const float* Wc  = (const float*)d_in[4];
    const float* W1  = (const float*)d_in[5];
    const float* W2  = (const float*)d_in[6];
    const float* g1  = (const float*)d_in[7];
    const float* b1  = (const float*)d_in[8];
    const float* g2  = (const float*)d_in[9];
    const float* b2  = (const float*)d_in[10];
    float* out = (float*)d_out;

    cudaFuncSetAttribute(k_fused, cudaFuncAttributeMaxDynamicSharedMemorySize, FSMEM);

    k_addpe<<<TT*EE/4/256, 256>>>(x, pe);
    k_cvtw2<<<(NL*EE*FFN/4)/256, 256>>>(W2);
    k_cvtw1<<<(NL*FFN*NQ/4)/256, 256>>>(W1);
    for (int l = 0; l < NL; l++) {
        k_attn<<<dim3(4, NH, BB), 512>>>(tha, l);
        k_comb_ln<<<TT/32, 256>>>(Wc, g1, b1, l);
        k_fused<<<TT/64, 512, FSMEM>>>(thf, g2, b2, out, l, (l == NL-1) ? 1 : 0);
    }
}